// round 1
// baseline (speedup 1.0000x reference)
#include <cuda_runtime.h>
#include <stdint.h>

// Problem: x [n,c,h,w] fp32, per (n,c) row of hw=4096 keep top-k by |x|.
// out = x where kept, x*(1-tau) where dropped.
// One CTA per row. Exact k-th |x| via 4-pass MSD radix select on abs bits.

constexpr int HW      = 4096;
constexpr int THREADS = 256;
constexpr int EPT     = HW / THREADS;   // 16 elements per thread (blocked)
constexpr int NWARP   = THREADS / 32;   // 8

__global__ __launch_bounds__(THREADS)
void topk_blend_kernel(const float* __restrict__ x,
                       const float* __restrict__ tau_p,
                       const int*   __restrict__ k_p,
                       float*       __restrict__ out)
{
    __shared__ uint32_t sdata[HW];            // raw fp32 bits of the row
    __shared__ uint32_t whist[NWARP][256];    // per-warp privatized histograms
    __shared__ uint32_t cnt[256];
    __shared__ uint32_t scan[256];
    __shared__ uint32_t s_prefix, s_krem;

    const int tid = threadIdx.x;
    const int wid = tid >> 5;
    const size_t base = (size_t)blockIdx.x * HW;

    // Blocked vectorized load: thread t owns row elements [t*16, t*16+16)
    const float4* __restrict__ xin = reinterpret_cast<const float4*>(x + base);
    #pragma unroll
    for (int i = 0; i < EPT / 4; i++) {
        float4 v = xin[tid * (EPT / 4) + i];
        uint4 u = make_uint4(__float_as_uint(v.x), __float_as_uint(v.y),
                             __float_as_uint(v.z), __float_as_uint(v.w));
        reinterpret_cast<uint4*>(sdata)[tid * (EPT / 4) + i] = u;
    }

    const float tau = __ldg(tau_p);
    const int   K   = __ldg(k_p);
    __syncthreads();

    uint32_t T      = 0;   // abs-bits of the K-th largest
    int      t_need = 0;   // how many elements == T to keep
    int      t_excl = 0;   // this thread's exclusive tie-rank offset

    if (K > 0 && K < HW) {
        uint32_t prefix = 0;
        uint32_t krem   = (uint32_t)K;

        #pragma unroll
        for (int pass = 0; pass < 4; pass++) {
            const int      shift  = 24 - 8 * pass;
            const uint32_t himask = (pass == 0) ? 0u : (0xFFFFFFFFu << (shift + 8));

            // zero all per-warp histogram bins
            #pragma unroll
            for (int b = 0; b < NWARP; b++) whist[b][tid] = 0;
            __syncthreads();

            // histogram over elements matching the determined prefix
            #pragma unroll
            for (int j = 0; j < EPT; j++) {
                uint32_t a = sdata[tid * EPT + j] & 0x7FFFFFFFu;
                if ((a & himask) == prefix)
                    atomicAdd(&whist[wid][(a >> shift) & 0xFFu], 1u);
            }
            __syncthreads();

            // reduce warp histograms
            uint32_t c = 0;
            #pragma unroll
            for (int w = 0; w < NWARP; w++) c += whist[w][tid];
            cnt[tid]  = c;
            scan[tid] = c;

            // inclusive suffix scan: scan[d] = count of digits >= d
            #pragma unroll
            for (int off = 1; off < 256; off <<= 1) {
                __syncthreads();
                uint32_t v = (tid + off < 256) ? scan[tid + off] : 0u;
                __syncthreads();
                scan[tid] += v;
            }
            __syncthreads();

            uint32_t incl  = scan[tid];
            uint32_t above = incl - c;             // count of digits > d
            if (above < krem && krem <= incl) {    // unique crossing digit
                s_prefix = prefix | ((uint32_t)tid << shift);
                s_krem   = krem - above;
            }
            __syncthreads();
            prefix = s_prefix;
            krem   = s_krem;
            __syncthreads();
        }
        T      = prefix;
        t_need = (int)krem;

        // Stable tie ordering (lowest index first): exclusive prefix scan of
        // per-thread ==T counts. Blocked layout => thread order == index order.
        int myeq = 0;
        #pragma unroll
        for (int j = 0; j < EPT; j++) {
            uint32_t a = sdata[tid * EPT + j] & 0x7FFFFFFFu;
            myeq += (a == T);
        }
        scan[tid] = (uint32_t)myeq;
        #pragma unroll
        for (int off = 1; off < 256; off <<= 1) {
            __syncthreads();
            uint32_t v = (tid >= off) ? scan[tid - off] : 0u;
            __syncthreads();
            scan[tid] += v;
        }
        __syncthreads();
        t_excl = (int)(scan[tid] - (uint32_t)myeq);
    }

    // Apply: out = kept ? x : x * (1 - tau)
    const float omt = 1.0f - tau;
    float4* __restrict__ yout = reinterpret_cast<float4*>(out + base);
    int rank = t_excl;
    #pragma unroll
    for (int i = 0; i < EPT / 4; i++) {
        uint4 u = reinterpret_cast<uint4*>(sdata)[tid * (EPT / 4) + i];
        uint32_t bs[4] = {u.x, u.y, u.z, u.w};
        float r[4];
        #pragma unroll
        for (int j = 0; j < 4; j++) {
            uint32_t b = bs[j];
            uint32_t a = b & 0x7FFFFFFFu;
            bool keep;
            if (K >= HW)      keep = true;
            else if (K <= 0)  keep = false;
            else if (a > T)   keep = true;
            else if (a == T)  { keep = (rank < t_need); rank++; }
            else              keep = false;
            float xv = __uint_as_float(b);
            r[j] = keep ? xv : xv * omt;
        }
        yout[tid * (EPT / 4) + i] = make_float4(r[0], r[1], r[2], r[3]);
    }
}

extern "C" void kernel_launch(void* const* d_in, const int* in_sizes, int n_in,
                              void* d_out, int out_size)
{
    const float* x     = (const float*)d_in[0];
    const float* tau   = (const float*)d_in[1];
    const int*   k     = (const int*)d_in[2];
    float*       out   = (float*)d_out;
    const int    rows  = in_sizes[0] / HW;   // n*c = 8192

    topk_blend_kernel<<<rows, THREADS>>>(x, tau, k, out);
}

// round 2
// speedup vs baseline: 3.1480x; 3.1480x over previous
#include <cuda_runtime.h>
#include <stdint.h>

// x [n,c,h,w] fp32; per (n,c) row of hw=4096 keep top-k by |x|.
// out = x (kept) or x*(1-tau) (dropped).  (sparse*tau + x*(1-tau) == x when kept)
// One CTA per row. Exact k-th |x| via 4-pass MSD radix select on abs bits,
// data held entirely in registers; smem only for histograms/combine words.

constexpr int HW      = 4096;
constexpr int THREADS = 256;
constexpr int EPT     = HW / THREADS;   // 16
constexpr int NWARP   = THREADS / 32;   // 8
constexpr unsigned FULL = 0xFFFFFFFFu;

__global__ __launch_bounds__(THREADS)
void topk_blend_kernel(const float* __restrict__ x,
                       const float* __restrict__ tau_p,
                       const int*   __restrict__ k_p,
                       float*       __restrict__ out)
{
    __shared__ uint32_t whist[NWARP][256];   // per-warp hist (pass 0); copy 0 for later passes
    __shared__ uint32_t wsum[NWARP];
    __shared__ uint32_t wtie[NWARP];
    __shared__ uint32_t s_prefix, s_krem;

    const int tid  = threadIdx.x;
    const int wid  = tid >> 5;
    const int lane = tid & 31;
    const size_t base = (size_t)blockIdx.x * HW;

    // Blocked vectorized load into registers: thread t owns elements [t*16, t*16+16)
    uint32_t av[EPT];     // abs bits
    uint32_t sgn = 0;     // bit j = sign bit of element j
    const float4* __restrict__ xin = reinterpret_cast<const float4*>(x + base);
    #pragma unroll
    for (int i = 0; i < EPT / 4; i++) {
        float4 v = xin[tid * (EPT / 4) + i];
        uint32_t b0 = __float_as_uint(v.x), b1 = __float_as_uint(v.y);
        uint32_t b2 = __float_as_uint(v.z), b3 = __float_as_uint(v.w);
        av[i*4+0] = b0 & 0x7FFFFFFFu;  sgn |= (b0 >> 31) << (i*4+0);
        av[i*4+1] = b1 & 0x7FFFFFFFu;  sgn |= (b1 >> 31) << (i*4+1);
        av[i*4+2] = b2 & 0x7FFFFFFFu;  sgn |= (b2 >> 31) << (i*4+2);
        av[i*4+3] = b3 & 0x7FFFFFFFu;  sgn |= (b3 >> 31) << (i*4+3);
    }

    const float tau = __ldg(tau_p);
    const int   K   = __ldg(k_p);

    uint32_t T      = 0;   // abs-bits of the K-th largest
    int      t_need = 0;   // #elements == T to keep
    int      t_excl = 0;   // this thread's exclusive tie rank

    if (K > 0 && K < HW) {
        uint32_t prefix = 0;
        uint32_t krem   = (uint32_t)K;

        #pragma unroll
        for (int pass = 0; pass < 4; pass++) {
            const int      shift  = 24 - 8 * pass;
            const uint32_t himask = (pass == 0) ? 0u : (FULL << (shift + 8));

            // zero histogram(s)
            if (pass == 0) {
                #pragma unroll
                for (int b = 0; b < NWARP; b++) whist[b][tid] = 0;
            } else {
                whist[0][tid] = 0;
            }
            __syncthreads();

            if (pass == 0) {
                // all elements active; digits concentrate in few bins ->
                // warp-aggregate via match_any to kill atomic serialization
                uint32_t* hist = whist[wid];
                #pragma unroll
                for (int j = 0; j < EPT; j++) {
                    uint32_t dig = av[j] >> 24;
                    unsigned m = __match_any_sync(FULL, dig);
                    if ((int)(__ffs(m) - 1) == lane)
                        atomicAdd(&hist[dig], (uint32_t)__popc(m));
                }
            } else {
                // few active elements; plain atomics into single copy
                #pragma unroll
                for (int j = 0; j < EPT; j++) {
                    uint32_t a = av[j];
                    if ((a & himask) == prefix)
                        atomicAdd(&whist[0][(a >> shift) & 0xFFu], 1u);
                }
            }
            __syncthreads();

            // bin count for bin = tid
            uint32_t c;
            if (pass == 0) {
                c = 0;
                #pragma unroll
                for (int w = 0; w < NWARP; w++) c += whist[w][tid];
            } else {
                c = whist[0][tid];
            }

            // warp-level inclusive suffix scan (bins base..base+31)
            uint32_t s = c;
            #pragma unroll
            for (int off = 1; off < 32; off <<= 1) {
                uint32_t v = __shfl_down_sync(FULL, s, off);
                if (lane + off < 32) s += v;
            }
            if (lane == 0) wsum[wid] = s;      // warp total
            __syncthreads();

            uint32_t hi = 0;
            #pragma unroll
            for (int w = 0; w < NWARP; w++) if (w > wid) hi += wsum[w];
            uint32_t incl  = s + hi;           // count of digits >= tid
            uint32_t above = incl - c;         // count of digits >  tid
            if (above < krem && krem <= incl) { // unique crossing digit
                s_prefix = prefix | ((uint32_t)tid << shift);
                s_krem   = krem - above;
            }
            __syncthreads();
            prefix = s_prefix;
            krem   = s_krem;
            // (next writes to whist/wsum/s_prefix are separated by >=2 barriers)
        }
        T      = prefix;
        t_need = (int)krem;

        // Stable tie order (lowest index first): exclusive scan of ==T counts.
        int myeq = 0;
        #pragma unroll
        for (int j = 0; j < EPT; j++) myeq += (av[j] == T);

        uint32_t e = (uint32_t)myeq;           // warp inclusive scan (ascending)
        #pragma unroll
        for (int off = 1; off < 32; off <<= 1) {
            uint32_t v = __shfl_up_sync(FULL, e, off);
            if (lane >= off) e += v;
        }
        if (lane == 31) wtie[wid] = e;         // warp total
        __syncthreads();
        uint32_t lo = 0;
        #pragma unroll
        for (int w = 0; w < NWARP; w++) if (w < wid) lo += wtie[w];
        t_excl = (int)(e - (uint32_t)myeq + lo);
    }

    // Apply: out = kept ? x : x*(1-tau)
    const float omt = 1.0f - tau;
    float4* __restrict__ yout = reinterpret_cast<float4*>(out + base);
    int rank = t_excl;
    const bool keepall = (K >= HW);
    const bool dropall = (K <= 0);
    #pragma unroll
    for (int i = 0; i < EPT / 4; i++) {
        float r[4];
        #pragma unroll
        for (int j = 0; j < 4; j++) {
            const int idx = i * 4 + j;
            uint32_t a = av[idx];
            bool keep;
            if (keepall)      keep = true;
            else if (dropall) keep = false;
            else if (a > T)   keep = true;
            else if (a == T)  { keep = (rank < t_need); rank++; }
            else              keep = false;
            float xv = __uint_as_float(a | (((sgn >> idx) & 1u) << 31));
            r[j] = keep ? xv : xv * omt;
        }
        yout[tid * (EPT / 4) + i] = make_float4(r[0], r[1], r[2], r[3]);
    }
}

extern "C" void kernel_launch(void* const* d_in, const int* in_sizes, int n_in,
                              void* d_out, int out_size)
{
    const float* x   = (const float*)d_in[0];
    const float* tau = (const float*)d_in[1];
    const int*   k   = (const int*)d_in[2];
    float*       out = (float*)d_out;
    const int    rows = in_sizes[0] / HW;   // n*c = 8192

    topk_blend_kernel<<<rows, THREADS>>>(x, tau, k, out);
}